// round 1
// baseline (speedup 1.0000x reference)
#include <cuda_runtime.h>

#define NN 100000
#define EE 3200000

// ---- scratch (device globals; no allocation allowed) ----
__device__ float g_dis[NN];          // rsqrt(deg)
__device__ float g_norm[EE];         // per-edge dis[src]*dis[dst]
__device__ float g_x[NN * 16];       // current block input features
__device__ float g_bufA[NN * 64];
__device__ float g_bufB[NN * 64];

// ---------------- degree / norm precompute ----------------
__global__ void k_init_deg() {
    int i = blockIdx.x * blockDim.x + threadIdx.x;
    if (i < NN) g_dis[i] = 1.0f;  // self-loop contributes 1
}

__global__ void k_count_deg(const int* __restrict__ dst) {
    int e = blockIdx.x * blockDim.x + threadIdx.x;
    if (e < EE) atomicAdd(&g_dis[dst[e]], 1.0f);
}

__global__ void k_rsqrt_deg() {
    int i = blockIdx.x * blockDim.x + threadIdx.x;
    if (i < NN) g_dis[i] = rsqrtf(g_dis[i]);
}

__global__ void k_edge_norm(const int* __restrict__ src, const int* __restrict__ dst) {
    int e = blockIdx.x * blockDim.x + threadIdx.x;
    if (e < EE) g_norm[e] = g_dis[src[e]] * g_dis[dst[e]];
}

// ---------------- aggregation y = A x ----------------
// Step 1: self-loop init  y[i] = x[i] * dis[i]^2
template <int D>
__global__ void k_selfinit(const float* __restrict__ xin, float* __restrict__ yout) {
    int t = blockIdx.x * blockDim.x + threadIdx.x;
    if (t >= NN * D) return;
    int i = t / D;
    float w = g_dis[i];
    yout[t] = xin[t] * w * w;
}

// Step 2: edge scatter  y[dst] += x[src] * norm
template <int D>
__global__ void k_agg(const float* __restrict__ xin, float* __restrict__ yout,
                      const int* __restrict__ src, const int* __restrict__ dst) {
    int t = blockIdx.x * blockDim.x + threadIdx.x;
    int e = t / D;
    int f = t % D;
    if (e >= EE) return;
    int s = src[e];
    int d = dst[e];
    float v = xin[s * D + f] * g_norm[e];
    atomicAdd(&yout[d * D + f], v);
}

// ---------------- small dense GEMM per node row ----------------
// y[i] = act( maybe_relu_bias(x[i]) @ W + maybe bias )
// INBR : apply relu(x + bin) to the input row (deferred bias+relu of previous layer)
// OUTBR: add bout and apply relu to the output row
template <int DIN, int DOUT, bool INBR, bool OUTBR>
__global__ void k_gemm(const float* __restrict__ xin, float* __restrict__ yout,
                       const float* __restrict__ W,
                       const float* __restrict__ bin,
                       const float* __restrict__ bout) {
    __shared__ float Ws[DIN * DOUT];
    __shared__ float bis[DIN];
    __shared__ float bos[DOUT];
    for (int k = threadIdx.x; k < DIN * DOUT; k += blockDim.x) Ws[k] = W[k];
    if (INBR) for (int k = threadIdx.x; k < DIN; k += blockDim.x) bis[k] = bin[k];
    if (OUTBR) for (int k = threadIdx.x; k < DOUT; k += blockDim.x) bos[k] = bout[k];
    __syncthreads();

    int i = blockIdx.x * blockDim.x + threadIdx.x;
    if (i >= NN) return;

    float acc[DOUT];
#pragma unroll
    for (int j = 0; j < DOUT; j++) acc[j] = OUTBR ? bos[j] : 0.0f;

#pragma unroll 4
    for (int k = 0; k < DIN; k++) {
        float xk = xin[i * DIN + k];
        if (INBR) xk = fmaxf(xk + bis[k], 0.0f);
#pragma unroll
        for (int j = 0; j < DOUT; j++) acc[j] += xk * Ws[k * DOUT + j];
    }

#pragma unroll
    for (int j = 0; j < DOUT; j++) {
        float v = acc[j];
        if (OUTBR) v = fmaxf(v, 0.0f);
        yout[i * DOUT + j] = v;
    }
}

// ---------------- softmax epilogue: out = softmax(w + b3, axis=1) ----------------
__global__ void k_softmax16(const float* __restrict__ win, const float* __restrict__ b,
                            float* __restrict__ out) {
    int i = blockIdx.x * blockDim.x + threadIdx.x;
    if (i >= NN) return;
    float v[16];
    float m = -1e30f;
#pragma unroll
    for (int f = 0; f < 16; f++) {
        v[f] = win[i * 16 + f] + b[f];
        m = fmaxf(m, v[f]);
    }
    float s = 0.0f;
#pragma unroll
    for (int f = 0; f < 16; f++) {
        v[f] = expf(v[f] - m);
        s += v[f];
    }
    float inv = 1.0f / s;
#pragma unroll
    for (int f = 0; f < 16; f++) out[i * 16 + f] = v[f] * inv;
}

// ---------------- launch ----------------
extern "C" void kernel_launch(void* const* d_in, const int* in_sizes, int n_in,
                              void* d_out, int out_size) {
    const float* x  = (const float*)d_in[0];
    const int*   ei = (const int*)d_in[1];
    const int*   src = ei;
    const int*   dst = ei + EE;
    const float* W1 = (const float*)d_in[2];
    const float* b1 = (const float*)d_in[3];
    const float* W2 = (const float*)d_in[4];
    const float* b2 = (const float*)d_in[5];
    const float* W3 = (const float*)d_in[6];
    const float* b3 = (const float*)d_in[7];
    float* out = (float*)d_out;

    float *pX, *pA, *pB;
    cudaGetSymbolAddress((void**)&pX, g_x);
    cudaGetSymbolAddress((void**)&pA, g_bufA);
    cudaGetSymbolAddress((void**)&pB, g_bufB);

    const int TB = 256;
    const int gN   = (NN + TB - 1) / TB;
    const int gE   = (EE + TB - 1) / TB;
    const int gN16 = (NN * 16 + TB - 1) / TB;
    const int gN32 = (NN * 32 + TB - 1) / TB;
    const int gE16 = (EE * 16 + TB - 1) / TB;   // 200000 blocks
    const int gE32 = (EE * 32 + TB - 1) / TB;   // 400000 blocks
    const int gG   = (NN + 127) / 128;

    // degree / norm
    k_init_deg<<<gN, TB>>>();
    k_count_deg<<<gE, TB>>>(dst);
    k_rsqrt_deg<<<gN, TB>>>();
    k_edge_norm<<<gE, TB>>>(src, dst);

    for (int blk = 0; blk < 5; blk++) {
        const float* xin = (blk == 0) ? x : pX;

        // layer1: y = A x (d=16), then t = relu(y @ W1 + b1) (d=64)
        k_selfinit<16><<<gN16, TB>>>(xin, pA);
        k_agg<16><<<gE16, TB>>>(xin, pA, src, dst);
        k_gemm<16, 64, false, true><<<gG, 128>>>(pA, pB, W1 + blk * 16 * 64,
                                                 nullptr, b1 + blk * 64);

        // layer2: h = t @ W2 (d=32), z = A h ; (bias b2 + relu deferred into layer3 GEMM)
        k_gemm<64, 32, false, false><<<gG, 128>>>(pB, pA, W2 + blk * 64 * 32,
                                                  nullptr, nullptr);
        k_selfinit<32><<<gN32, TB>>>(pA, pB);
        k_agg<32><<<gE32, TB>>>(pA, pB, src, dst);

        // layer3: h3 = relu(z + b2) @ W3 (d=16), w = A h3, out = softmax(w + b3)
        k_gemm<32, 16, true, false><<<gG, 128>>>(pB, pA, W3 + blk * 32 * 16,
                                                 b2 + blk * 32, nullptr);
        k_selfinit<16><<<gN16, TB>>>(pA, pB);
        k_agg<16><<<gE16, TB>>>(pA, pB, src, dst);

        float* xo = (blk == 4) ? out : pX;
        k_softmax16<<<gN, TB>>>(pB, b3 + blk * 16, xo);
    }
}

// round 2
// speedup vs baseline: 2.7411x; 2.7411x over previous
#include <cuda_runtime.h>

#define NN 100000
#define EE 3200000
#define NBLK ((NN + 1023) / 1024)   // 98 scan blocks

// ---- scratch (device globals; no allocation allowed) ----
__device__ int   g_cnt[NN];          // in-degree histogram (excl. self loop)
__device__ int   g_rowptr[NN + 1];   // CSR row pointers
__device__ int   g_blocksum[NBLK];
__device__ int   g_cur[NN];          // scatter cursors
__device__ int   g_csr_src[EE];      // CSR column indices (src node)
__device__ float g_csr_w[EE];        // per-edge norm dis[src]*dis[dst]
__device__ float g_dis[NN];          // rsqrt(deg)
__device__ float g_x[NN * 16];       // block-to-block features
__device__ float g_bufA[NN * 64];
__device__ float g_bufB[NN * 64];

__device__ __forceinline__ float4 f4_shfl_xor_add(float4 v, int m) {
    v.x += __shfl_xor_sync(0xffffffffu, v.x, m);
    v.y += __shfl_xor_sync(0xffffffffu, v.y, m);
    v.z += __shfl_xor_sync(0xffffffffu, v.z, m);
    v.w += __shfl_xor_sync(0xffffffffu, v.w, m);
    return v;
}

// ---------------- CSR build ----------------
__global__ void k_zero_cnt() {
    int i = blockIdx.x * blockDim.x + threadIdx.x;
    if (i < NN) g_cnt[i] = 0;
}

__global__ void k_hist(const int* __restrict__ dst) {
    int e = blockIdx.x * blockDim.x + threadIdx.x;
    if (e < EE) atomicAdd(&g_cnt[dst[e]], 1);
}

// block-level inclusive scan (1024/block), writes exclusive-in-block to rowptr
__global__ void k_scan1() {
    __shared__ int sh[1024];
    int i = blockIdx.x * 1024 + threadIdx.x;
    int v = (i < NN) ? g_cnt[i] : 0;
    sh[threadIdx.x] = v;
    __syncthreads();
#pragma unroll
    for (int off = 1; off < 1024; off <<= 1) {
        int t = (threadIdx.x >= off) ? sh[threadIdx.x - off] : 0;
        __syncthreads();
        sh[threadIdx.x] += t;
        __syncthreads();
    }
    if (i < NN) g_rowptr[i] = sh[threadIdx.x] - v;   // exclusive within block
    if (threadIdx.x == 1023) g_blocksum[blockIdx.x] = sh[1023];
}

__global__ void k_scan2() {
    if (threadIdx.x == 0 && blockIdx.x == 0) {
        int acc = 0;
        for (int b = 0; b < NBLK; b++) {
            int t = g_blocksum[b];
            g_blocksum[b] = acc;
            acc += t;
        }
    }
}

__global__ void k_finalize() {
    int i = blockIdx.x * blockDim.x + threadIdx.x;
    if (i >= NN) return;
    int r = g_rowptr[i] + g_blocksum[i >> 10];
    g_rowptr[i] = r;
    g_cur[i] = r;
    g_dis[i] = rsqrtf((float)g_cnt[i] + 1.0f);   // +1 self loop
    if (i == 0) g_rowptr[NN] = EE;
}

__global__ void k_scatter(const int* __restrict__ src, const int* __restrict__ dst) {
    int e = blockIdx.x * blockDim.x + threadIdx.x;
    if (e >= EE) return;
    int s = src[e], d = dst[e];
    int pos = atomicAdd(&g_cur[d], 1);
    g_csr_src[pos] = s;
    g_csr_w[pos] = g_dis[s] * g_dis[d];
}

// ---------------- CSR aggregation: y = A x ----------------
// D=16: warp per node. lane = (edge-slot ei = lane>>2, quarter q = lane&3).
// 8 edges in flight; float4 row-quarter gathers. Optional fused softmax(v + b).
template <bool SM>
__global__ void k_agg16(const float* __restrict__ xin, float* __restrict__ yout,
                        const float* __restrict__ bsm) {
    int warp = (blockIdx.x * blockDim.x + threadIdx.x) >> 5;
    if (warp >= NN) return;
    int lane = threadIdx.x & 31;
    int q = lane & 3;
    int ei = lane >> 2;
    int beg = g_rowptr[warp];
    int end = g_rowptr[warp + 1];
    const float4* __restrict__ x4 = (const float4*)xin;

    float4 acc = make_float4(0.f, 0.f, 0.f, 0.f);
    if (ei == 0) {  // self loop term: x[node] * dis^2
        float w = g_dis[warp]; w *= w;
        float4 xv = x4[warp * 4 + q];
        acc.x = xv.x * w; acc.y = xv.y * w; acc.z = xv.z * w; acc.w = xv.w * w;
    }
    for (int e = beg + ei; e < end; e += 8) {
        int s = g_csr_src[e];
        float nw = g_csr_w[e];
        float4 xv = x4[s * 4 + q];
        acc.x += xv.x * nw; acc.y += xv.y * nw; acc.z += xv.z * nw; acc.w += xv.w * nw;
    }
    acc = f4_shfl_xor_add(acc, 4);
    acc = f4_shfl_xor_add(acc, 8);
    acc = f4_shfl_xor_add(acc, 16);
    // now every lane holds the full sum for quarter (lane&3)

    if (SM) {
        acc.x += bsm[q * 4 + 0];
        acc.y += bsm[q * 4 + 1];
        acc.z += bsm[q * 4 + 2];
        acc.w += bsm[q * 4 + 3];
        float m = fmaxf(fmaxf(acc.x, acc.y), fmaxf(acc.z, acc.w));
        m = fmaxf(m, __shfl_xor_sync(0xffffffffu, m, 1));
        m = fmaxf(m, __shfl_xor_sync(0xffffffffu, m, 2));
        acc.x = __expf(acc.x - m);
        acc.y = __expf(acc.y - m);
        acc.z = __expf(acc.z - m);
        acc.w = __expf(acc.w - m);
        float s = acc.x + acc.y + acc.z + acc.w;
        s += __shfl_xor_sync(0xffffffffu, s, 1);
        s += __shfl_xor_sync(0xffffffffu, s, 2);
        float inv = 1.0f / s;
        acc.x *= inv; acc.y *= inv; acc.z *= inv; acc.w *= inv;
    }
    if (lane < 4) ((float4*)yout)[warp * 4 + q] = acc;
}

// D=32: warp per node. lane = (edge-slot ei = lane>>3, eighth q = lane&7).
__global__ void k_agg32(const float* __restrict__ xin, float* __restrict__ yout) {
    int warp = (blockIdx.x * blockDim.x + threadIdx.x) >> 5;
    if (warp >= NN) return;
    int lane = threadIdx.x & 31;
    int q = lane & 7;
    int ei = lane >> 3;
    int beg = g_rowptr[warp];
    int end = g_rowptr[warp + 1];
    const float4* __restrict__ x4 = (const float4*)xin;

    float4 acc = make_float4(0.f, 0.f, 0.f, 0.f);
    if (ei == 0) {
        float w = g_dis[warp]; w *= w;
        float4 xv = x4[warp * 8 + q];
        acc.x = xv.x * w; acc.y = xv.y * w; acc.z = xv.z * w; acc.w = xv.w * w;
    }
    for (int e = beg + ei; e < end; e += 4) {
        int s = g_csr_src[e];
        float nw = g_csr_w[e];
        float4 xv = x4[s * 8 + q];
        acc.x += xv.x * nw; acc.y += xv.y * nw; acc.z += xv.z * nw; acc.w += xv.w * nw;
    }
    acc = f4_shfl_xor_add(acc, 8);
    acc = f4_shfl_xor_add(acc, 16);
    if (lane < 8) ((float4*)yout)[warp * 8 + q] = acc;
}

// ---------------- small dense GEMM per node row ----------------
template <int DIN, int DOUT, bool INBR, bool OUTBR>
__global__ void k_gemm(const float* __restrict__ xin, float* __restrict__ yout,
                       const float* __restrict__ W,
                       const float* __restrict__ bin,
                       const float* __restrict__ bout) {
    __shared__ float Ws[DIN * DOUT];
    __shared__ float bis[DIN];
    __shared__ float bos[DOUT];
    for (int k = threadIdx.x; k < DIN * DOUT; k += blockDim.x) Ws[k] = W[k];
    if (INBR) for (int k = threadIdx.x; k < DIN; k += blockDim.x) bis[k] = bin[k];
    if (OUTBR) for (int k = threadIdx.x; k < DOUT; k += blockDim.x) bos[k] = bout[k];
    __syncthreads();

    int i = blockIdx.x * blockDim.x + threadIdx.x;
    if (i >= NN) return;

    float acc[DOUT];
#pragma unroll
    for (int j = 0; j < DOUT; j++) acc[j] = OUTBR ? bos[j] : 0.0f;

#pragma unroll 4
    for (int k = 0; k < DIN; k++) {
        float xk = xin[i * DIN + k];
        if (INBR) xk = fmaxf(xk + bis[k], 0.0f);
#pragma unroll
        for (int j = 0; j < DOUT; j++) acc[j] += xk * Ws[k * DOUT + j];
    }

#pragma unroll
    for (int j = 0; j < DOUT; j++) {
        float v = acc[j];
        if (OUTBR) v = fmaxf(v, 0.0f);
        yout[i * DOUT + j] = v;
    }
}

// ---------------- launch ----------------
extern "C" void kernel_launch(void* const* d_in, const int* in_sizes, int n_in,
                              void* d_out, int out_size) {
    const float* x  = (const float*)d_in[0];
    const int*   ei = (const int*)d_in[1];
    const int*   src = ei;
    const int*   dst = ei + EE;
    const float* W1 = (const float*)d_in[2];
    const float* b1 = (const float*)d_in[3];
    const float* W2 = (const float*)d_in[4];
    const float* b2 = (const float*)d_in[5];
    const float* W3 = (const float*)d_in[6];
    const float* b3 = (const float*)d_in[7];
    float* out = (float*)d_out;

    float *pX, *pA, *pB;
    cudaGetSymbolAddress((void**)&pX, g_x);
    cudaGetSymbolAddress((void**)&pA, g_bufA);
    cudaGetSymbolAddress((void**)&pB, g_bufB);

    const int TB = 256;
    const int gN = (NN + TB - 1) / TB;
    const int gE = (EE + TB - 1) / TB;
    const int gW = (NN * 32 + TB - 1) / TB;   // warp-per-node grids (12500 blocks)
    const int gG = (NN + 127) / 128;

    // ---- CSR build (per launch; deterministic work) ----
    k_zero_cnt<<<gN, TB>>>();
    k_hist<<<gE, TB>>>(dst);
    k_scan1<<<NBLK, 1024>>>();
    k_scan2<<<1, 32>>>();
    k_finalize<<<gN, TB>>>();
    k_scatter<<<gE, TB>>>(src, dst);

    for (int blk = 0; blk < 5; blk++) {
        const float* xin = (blk == 0) ? x : pX;

        // layer1: y = A x (d=16), then t = relu(y @ W1 + b1) (d=64)
        k_agg16<false><<<gW, TB>>>(xin, pA, nullptr);
        k_gemm<16, 64, false, true><<<gG, 128>>>(pA, pB, W1 + blk * 16 * 64,
                                                 nullptr, b1 + blk * 64);

        // layer2: h = t @ W2 (d=32), z = A h ; (bias b2 + relu deferred)
        k_gemm<64, 32, false, false><<<gG, 128>>>(pB, pA, W2 + blk * 64 * 32,
                                                  nullptr, nullptr);
        k_agg32<<<gW, TB>>>(pA, pB);

        // layer3: h3 = relu(z + b2) @ W3 (d=16), out = softmax(A h3 + b3)
        k_gemm<32, 16, true, false><<<gG, 128>>>(pB, pA, W3 + blk * 32 * 16,
                                                 b2 + blk * 32, nullptr);
        float* xo = (blk == 4) ? out : pX;
        k_agg16<true><<<gW, TB>>>(pA, xo, b3 + blk * 16);
    }
}

// round 3
// speedup vs baseline: 3.8698x; 1.4118x over previous
#include <cuda_runtime.h>
#include <cuda_fp16.h>

#define NN 100000
#define EE 3200000
#define NBLK ((NN + 1023) / 1024)   // 98 scan blocks

// ---- scratch (device globals; no allocation allowed) ----
__device__ int    g_cnt[NN];
__device__ int    g_rowptr[NN + 1];
__device__ int    g_blocksum[NBLK];
__device__ int    g_cur[NN];
__device__ int    g_csr_src[EE];
__device__ float  g_dis[NN];           // rsqrt(deg)
__device__ __half g_hx[NN * 16];       // x~ between blocks (dis-scaled, fp16)
__device__ __half g_h1[NN * 32];       // y~ (d32, dis-scaled, fp16)
__device__ __half g_h2[NN * 16];       // h~ (d16, dis-scaled, fp16)
__device__ float  g_f[NN * 32];        // fp32 per-node scratch

// ---------------- helpers ----------------
__device__ __forceinline__ void acc_h8(uint4 u, float* a) {
    float2 f;
    f = __half22float2(*reinterpret_cast<__half2*>(&u.x)); a[0] += f.x; a[1] += f.y;
    f = __half22float2(*reinterpret_cast<__half2*>(&u.y)); a[2] += f.x; a[3] += f.y;
    f = __half22float2(*reinterpret_cast<__half2*>(&u.z)); a[4] += f.x; a[5] += f.y;
    f = __half22float2(*reinterpret_cast<__half2*>(&u.w)); a[6] += f.x; a[7] += f.y;
}

__device__ __forceinline__ void red8(float* a, int m) {
#pragma unroll
    for (int t = 0; t < 8; t++) a[t] += __shfl_xor_sync(0xffffffffu, a[t], m);
}

// ---------------- CSR build ----------------
__global__ void k_zero_cnt() {
    int i = blockIdx.x * blockDim.x + threadIdx.x;
    if (i < NN) g_cnt[i] = 0;
}

__global__ void k_hist(const int* __restrict__ dst) {
    int e = blockIdx.x * blockDim.x + threadIdx.x;
    if (e < EE) atomicAdd(&g_cnt[dst[e]], 1);
}

__global__ void k_scan1() {
    __shared__ int sh[1024];
    int i = blockIdx.x * 1024 + threadIdx.x;
    int v = (i < NN) ? g_cnt[i] : 0;
    sh[threadIdx.x] = v;
    __syncthreads();
#pragma unroll
    for (int off = 1; off < 1024; off <<= 1) {
        int t = (threadIdx.x >= off) ? sh[threadIdx.x - off] : 0;
        __syncthreads();
        sh[threadIdx.x] += t;
        __syncthreads();
    }
    if (i < NN) g_rowptr[i] = sh[threadIdx.x] - v;
    if (threadIdx.x == 1023) g_blocksum[blockIdx.x] = sh[1023];
}

__global__ void k_scan2() {
    if (threadIdx.x == 0 && blockIdx.x == 0) {
        int acc = 0;
        for (int b = 0; b < NBLK; b++) {
            int t = g_blocksum[b];
            g_blocksum[b] = acc;
            acc += t;
        }
    }
}

__global__ void k_finalize() {
    int i = blockIdx.x * blockDim.x + threadIdx.x;
    if (i >= NN) return;
    int r = g_rowptr[i] + g_blocksum[i >> 10];
    g_rowptr[i] = r;
    g_cur[i] = r;
    g_dis[i] = rsqrtf((float)g_cnt[i] + 1.0f);
    if (i == 0) g_rowptr[NN] = EE;
}

__global__ void k_scatter(const int* __restrict__ src, const int* __restrict__ dst) {
    int e = blockIdx.x * blockDim.x + threadIdx.x;
    if (e >= EE) return;
    int pos = atomicAdd(&g_cur[dst[e]], 1);
    g_csr_src[pos] = src[e];
}

// prescale: x~ = half(dis[i] * x[i])   (d=16)
__global__ void k_prescale(const float* __restrict__ x) {
    int i = blockIdx.x * blockDim.x + threadIdx.x;
    if (i >= NN) return;
    float d = g_dis[i];
    __half2* o = ((__half2*)g_hx) + i * 8;
#pragma unroll
    for (int j = 0; j < 8; j++) {
        float a = x[i * 16 + 2 * j] * d;
        float b = x[i * 16 + 2 * j + 1] * d;
        o[j] = __floats2half2_rn(a, b);
    }
}

// ---------------- aggregation y = dis[d]*(x~[d] + sum x~[src]) ----------------
// D=16 (fp16 rows, 32B): 2 lanes/row-half, 16 edges in flight.
// MODE 0: write fp32 (d16) scaled by dis[d]
// MODE 1: softmax(v + b) -> write half scaled by dis[d]  (next block's x~)
// MODE 2: softmax(v + b) -> write fp32 unscaled          (final output)
template <int MODE>
__global__ void k_agg16h(const __half* __restrict__ xin, void* __restrict__ yout,
                         const float* __restrict__ bsm) {
    int warp = (blockIdx.x * blockDim.x + threadIdx.x) >> 5;
    if (warp >= NN) return;
    int lane = threadIdx.x & 31;
    int h = lane & 1;
    int ei = lane >> 1;
    int beg = g_rowptr[warp];
    int end = g_rowptr[warp + 1];
    const uint4* __restrict__ x4 = (const uint4*)xin;

    float a[8] = {0, 0, 0, 0, 0, 0, 0, 0};
    if (ei == 0) acc_h8(x4[warp * 2 + h], a);        // self loop
    for (int e = beg + ei; e < end; e += 16)
        acc_h8(x4[g_csr_src[e] * 2 + h], a);

    red8(a, 2); red8(a, 4); red8(a, 8); red8(a, 16);

    float d = g_dis[warp];
#pragma unroll
    for (int t = 0; t < 8; t++) a[t] *= d;

    if (MODE == 0) {
        if (lane < 2) {
            float4* o = (float4*)yout;
            o[warp * 4 + h * 2 + 0] = make_float4(a[0], a[1], a[2], a[3]);
            o[warp * 4 + h * 2 + 1] = make_float4(a[4], a[5], a[6], a[7]);
        }
        return;
    }
    // softmax over 16 features split across h=0/1
#pragma unroll
    for (int t = 0; t < 8; t++) a[t] += bsm[h * 8 + t];
    float m = a[0];
#pragma unroll
    for (int t = 1; t < 8; t++) m = fmaxf(m, a[t]);
    m = fmaxf(m, __shfl_xor_sync(0xffffffffu, m, 1));
    float s = 0.0f;
#pragma unroll
    for (int t = 0; t < 8; t++) { a[t] = __expf(a[t] - m); s += a[t]; }
    s += __shfl_xor_sync(0xffffffffu, s, 1);
    float inv = 1.0f / s;
#pragma unroll
    for (int t = 0; t < 8; t++) a[t] *= inv;

    if (MODE == 1) {
        if (lane < 2) {
            uint4 u;
            *reinterpret_cast<__half2*>(&u.x) = __floats2half2_rn(a[0] * d, a[1] * d);
            *reinterpret_cast<__half2*>(&u.y) = __floats2half2_rn(a[2] * d, a[3] * d);
            *reinterpret_cast<__half2*>(&u.z) = __floats2half2_rn(a[4] * d, a[5] * d);
            *reinterpret_cast<__half2*>(&u.w) = __floats2half2_rn(a[6] * d, a[7] * d);
            ((uint4*)yout)[warp * 2 + h] = u;
        }
    } else {
        if (lane < 2) {
            float4* o = (float4*)yout;
            o[warp * 4 + h * 2 + 0] = make_float4(a[0], a[1], a[2], a[3]);
            o[warp * 4 + h * 2 + 1] = make_float4(a[4], a[5], a[6], a[7]);
        }
    }
}

// D=32 (fp16 rows, 64B): 4 lanes/row-quarter, 8 edges in flight. fp32 out, scaled.
__global__ void k_agg32h(const __half* __restrict__ xin, float* __restrict__ yout) {
    int warp = (blockIdx.x * blockDim.x + threadIdx.x) >> 5;
    if (warp >= NN) return;
    int lane = threadIdx.x & 31;
    int h = lane & 3;
    int ei = lane >> 2;
    int beg = g_rowptr[warp];
    int end = g_rowptr[warp + 1];
    const uint4* __restrict__ x4 = (const uint4*)xin;

    float a[8] = {0, 0, 0, 0, 0, 0, 0, 0};
    if (ei == 0) acc_h8(x4[warp * 4 + h], a);
    for (int e = beg + ei; e < end; e += 8)
        acc_h8(x4[g_csr_src[e] * 4 + h], a);

    red8(a, 4); red8(a, 8); red8(a, 16);

    float d = g_dis[warp];
    if (lane < 4) {
        float4* o = (float4*)yout;
        o[warp * 8 + h * 2 + 0] = make_float4(a[0] * d, a[1] * d, a[2] * d, a[3] * d);
        o[warp * 8 + h * 2 + 1] = make_float4(a[4] * d, a[5] * d, a[6] * d, a[7] * d);
    }
}

// ---------------- fused per-node GEMM: z = relu(y@W1 + b1) @ W2, out half dis-scaled ----------------
__global__ void k_gemm_fused(const float* __restrict__ yin, __half* __restrict__ zout,
                             const float* __restrict__ W1, const float* __restrict__ b1,
                             const float* __restrict__ W2) {
    __shared__ float W1s[16 * 64];
    __shared__ float W2s[64 * 32];
    __shared__ float b1s[64];
    for (int k = threadIdx.x; k < 16 * 64; k += blockDim.x) W1s[k] = W1[k];
    for (int k = threadIdx.x; k < 64 * 32; k += blockDim.x) W2s[k] = W2[k];
    for (int k = threadIdx.x; k < 64; k += blockDim.x) b1s[k] = b1[k];
    __syncthreads();

    int i = blockIdx.x * blockDim.x + threadIdx.x;
    if (i >= NN) return;

    float xr[16];
#pragma unroll
    for (int m = 0; m < 4; m++) {
        float4 v = ((const float4*)yin)[i * 4 + m];
        xr[m * 4 + 0] = v.x; xr[m * 4 + 1] = v.y; xr[m * 4 + 2] = v.z; xr[m * 4 + 3] = v.w;
    }
    float z[32];
#pragma unroll
    for (int j = 0; j < 32; j++) z[j] = 0.0f;

    for (int k = 0; k < 64; k++) {
        float t = b1s[k];
#pragma unroll
        for (int m = 0; m < 16; m++) t += xr[m] * W1s[m * 64 + k];
        t = fmaxf(t, 0.0f);
#pragma unroll
        for (int j = 0; j < 32; j++) z[j] += t * W2s[k * 32 + j];
    }

    float d = g_dis[i];
    __half2* o = ((__half2*)zout) + i * 16;
#pragma unroll
    for (int j = 0; j < 16; j++)
        o[j] = __floats2half2_rn(z[2 * j] * d, z[2 * j + 1] * d);
}

// ---------------- gemm3: h = relu(z + b2) @ W3, out half dis-scaled (d16) ----------------
__global__ void k_gemm3(const float* __restrict__ zin, __half* __restrict__ hout,
                        const float* __restrict__ b2, const float* __restrict__ W3) {
    __shared__ float W3s[32 * 16];
    __shared__ float b2s[32];
    for (int k = threadIdx.x; k < 32 * 16; k += blockDim.x) W3s[k] = W3[k];
    for (int k = threadIdx.x; k < 32; k += blockDim.x) b2s[k] = b2[k];
    __syncthreads();

    int i = blockIdx.x * blockDim.x + threadIdx.x;
    if (i >= NN) return;

    float acc[16];
#pragma unroll
    for (int j = 0; j < 16; j++) acc[j] = 0.0f;

#pragma unroll
    for (int m = 0; m < 8; m++) {
        float4 v = ((const float4*)zin)[i * 8 + m];
        float vv[4] = {v.x, v.y, v.z, v.w};
#pragma unroll
        for (int q = 0; q < 4; q++) {
            int k = m * 4 + q;
            float t = fmaxf(vv[q] + b2s[k], 0.0f);
#pragma unroll
            for (int j = 0; j < 16; j++) acc[j] += t * W3s[k * 16 + j];
        }
    }

    float d = g_dis[i];
    __half2* o = ((__half2*)hout) + i * 8;
#pragma unroll
    for (int j = 0; j < 8; j++)
        o[j] = __floats2half2_rn(acc[2 * j] * d, acc[2 * j + 1] * d);
}

// ---------------- launch ----------------
extern "C" void kernel_launch(void* const* d_in, const int* in_sizes, int n_in,
                              void* d_out, int out_size) {
    const float* x  = (const float*)d_in[0];
    const int*   ei = (const int*)d_in[1];
    const int*   src = ei;
    const int*   dst = ei + EE;
    const float* W1 = (const float*)d_in[2];
    const float* b1 = (const float*)d_in[3];
    const float* W2 = (const float*)d_in[4];
    const float* b2 = (const float*)d_in[5];
    const float* W3 = (const float*)d_in[6];
    const float* b3 = (const float*)d_in[7];
    float* out = (float*)d_out;

    __half *pHX, *pH1, *pH2;
    float *pF;
    cudaGetSymbolAddress((void**)&pHX, g_hx);
    cudaGetSymbolAddress((void**)&pH1, g_h1);
    cudaGetSymbolAddress((void**)&pH2, g_h2);
    cudaGetSymbolAddress((void**)&pF, g_f);

    const int TB = 256;
    const int gN = (NN + TB - 1) / TB;
    const int gE = (EE + TB - 1) / TB;
    const int gW = (NN * 32 + TB - 1) / TB;   // warp-per-node
    const int gG = (NN + 127) / 128;

    // CSR build + prescale
    k_zero_cnt<<<gN, TB>>>();
    k_hist<<<gE, TB>>>(dst);
    k_scan1<<<NBLK, 1024>>>();
    k_scan2<<<1, 32>>>();
    k_finalize<<<gN, TB>>>();
    k_scatter<<<gE, TB>>>(src, dst);
    k_prescale<<<gG, 128>>>(x);

    for (int blk = 0; blk < 5; blk++) {
        // layer1 agg (d16): y = dis*(sum x~)  [fp32]
        k_agg16h<0><<<gW, TB>>>(pHX, pF, nullptr);
        // fused gemm 16->64->32, relu, out = dis * (relu(yW1+b1)W2)  [fp16]
        k_gemm_fused<<<gG, 128>>>(pF, pH1, W1 + blk * 16 * 64, b1 + blk * 64,
                                  W2 + blk * 64 * 32);
        // layer2 agg (d32): z = dis*(sum y~)  [fp32]
        k_agg32h<<<gW, TB>>>(pH1, pF);
        // gemm3: h~ = dis * (relu(z+b2)W3)  [fp16]
        k_gemm3<<<gG, 128>>>(pF, pH2, b2 + blk * 32, W3 + blk * 32 * 16);
        // layer3 agg (d16) + softmax
        if (blk == 4)
            k_agg16h<2><<<gW, TB>>>(pH2, out, b3 + blk * 16);
        else
            k_agg16h<1><<<gW, TB>>>(pH2, pHX, b3 + blk * 16);
    }
}

// round 5
// speedup vs baseline: 4.0061x; 1.0352x over previous
#include <cuda_runtime.h>
#include <cuda_fp16.h>

#define NN 100000
#define EE 3200000
#define NBLK ((NN + 1023) / 1024)   // 98 scan blocks

// ---- scratch (device globals; no allocation allowed) ----
__device__ int    g_cnt[NN];
__device__ int    g_rowptr[NN + 1];
__device__ int    g_blocksum[NBLK];
__device__ int    g_cur[NN];
__device__ int    g_csr_src[EE];
__device__ float  g_dis[NN];           // rsqrt(deg)
__device__ __half g_hx[NN * 16];       // x~ between blocks (dis-scaled, fp16)
__device__ __half g_h1[NN * 32];       // y~ (d32, dis-scaled, fp16)
__device__ __half g_h2[NN * 16];       // h~ (d16, dis-scaled, fp16)
__device__ float  g_f[NN * 32];        // fp32 per-node scratch

// ---------------- helpers ----------------
__device__ __forceinline__ void acc_h8(uint4 u, float* a) {
    float2 f;
    f = __half22float2(*reinterpret_cast<__half2*>(&u.x)); a[0] += f.x; a[1] += f.y;
    f = __half22float2(*reinterpret_cast<__half2*>(&u.y)); a[2] += f.x; a[3] += f.y;
    f = __half22float2(*reinterpret_cast<__half2*>(&u.z)); a[4] += f.x; a[5] += f.y;
    f = __half22float2(*reinterpret_cast<__half2*>(&u.w)); a[6] += f.x; a[7] += f.y;
}

__device__ __forceinline__ void red8(float* a, int m) {
#pragma unroll
    for (int t = 0; t < 8; t++) a[t] += __shfl_xor_sync(0xffffffffu, a[t], m);
}

// ---------------- CSR build ----------------
__global__ void k_hist(const int* __restrict__ dst) {
    int e = blockIdx.x * blockDim.x + threadIdx.x;
    if (e < EE) atomicAdd(&g_cnt[dst[e]], 1);
}

__global__ void k_scan1() {
    __shared__ int sh[1024];
    int i = blockIdx.x * 1024 + threadIdx.x;
    int v = (i < NN) ? g_cnt[i] : 0;
    sh[threadIdx.x] = v;
    __syncthreads();
#pragma unroll
    for (int off = 1; off < 1024; off <<= 1) {
        int t = (threadIdx.x >= off) ? sh[threadIdx.x - off] : 0;
        __syncthreads();
        sh[threadIdx.x] += t;
        __syncthreads();
    }
    if (i < NN) g_rowptr[i] = sh[threadIdx.x] - v;
    if (threadIdx.x == 1023) g_blocksum[blockIdx.x] = sh[1023];
}

// one-warp shuffle scan over NBLK block sums (exclusive)
__global__ void k_scan2() {
    int lane = threadIdx.x;
    int acc = 0;
    for (int base = 0; base < NBLK; base += 32) {
        int i = base + lane;
        int orig = (i < NBLK) ? g_blocksum[i] : 0;
        int v = orig;
#pragma unroll
        for (int off = 1; off < 32; off <<= 1) {
            int t = __shfl_up_sync(0xffffffffu, v, off);
            if (lane >= off) v += t;
        }
        if (i < NBLK) g_blocksum[i] = acc + v - orig;
        acc += __shfl_sync(0xffffffffu, v, 31);
    }
}

__global__ void k_finalize() {
    int i = blockIdx.x * blockDim.x + threadIdx.x;
    if (i >= NN) return;
    int r = g_rowptr[i] + g_blocksum[i >> 10];
    g_rowptr[i] = r;
    g_cur[i] = r;
    g_dis[i] = rsqrtf((float)g_cnt[i] + 1.0f);
    if (i == 0) g_rowptr[NN] = EE;
}

__global__ void k_scatter(const int* __restrict__ src, const int* __restrict__ dst) {
    int e = blockIdx.x * blockDim.x + threadIdx.x;
    if (e >= EE) return;
    int pos = atomicAdd(&g_cur[dst[e]], 1);
    g_csr_src[pos] = src[e];
}

// prescale: x~ = half(dis[i] * x[i])   (d=16)
__global__ void k_prescale(const float* __restrict__ x) {
    int i = blockIdx.x * blockDim.x + threadIdx.x;
    if (i >= NN) return;
    float d = g_dis[i];
    __half2* o = ((__half2*)g_hx) + i * 8;
#pragma unroll
    for (int j = 0; j < 8; j++) {
        float a = x[i * 16 + 2 * j] * d;
        float b = x[i * 16 + 2 * j + 1] * d;
        o[j] = __floats2half2_rn(a, b);
    }
}

// ---------------- aggregation y = dis[d]*(x~[d] + sum x~[src]) ----------------
// D=16 (fp16 rows, 32B): 2 lanes/row-half, 2-wide pipelined -> 32 edges in flight.
// MODE 0: write fp32 (d16) scaled by dis[d]
// MODE 1: softmax(v + b) -> write half scaled by dis[d]  (next block's x~)
// MODE 2: softmax(v + b) -> write fp32 unscaled          (final output)
template <int MODE>
__global__ void k_agg16h(const __half* __restrict__ xin, void* __restrict__ yout,
                         const float* __restrict__ bsm) {
    int warp = (blockIdx.x * blockDim.x + threadIdx.x) >> 5;
    if (warp >= NN) return;
    int lane = threadIdx.x & 31;
    int h = lane & 1;
    int ei = lane >> 1;
    int beg = __ldg(&g_rowptr[warp]);
    int end = __ldg(&g_rowptr[warp + 1]);
    const uint4* __restrict__ x4 = (const uint4*)xin;

    float a[8] = {0, 0, 0, 0, 0, 0, 0, 0};
    if (ei == 0) acc_h8(x4[warp * 2 + h], a);        // self loop

    for (int e = beg + ei; e < end; e += 32) {
        int eb = e + 16;
        bool vb = eb < end;
        int sa = __ldg(&g_csr_src[e]);
        int sb = vb ? __ldg(&g_csr_src[eb]) : 0;
        uint4 ra = x4[sa * 2 + h];
        uint4 rb = x4[sb * 2 + h];
        acc_h8(ra, a);
        if (vb) acc_h8(rb, a);
    }

    red8(a, 2); red8(a, 4); red8(a, 8); red8(a, 16);

    float d = g_dis[warp];
#pragma unroll
    for (int t = 0; t < 8; t++) a[t] *= d;

    if (MODE == 0) {
        if (lane < 2) {
            float4* o = (float4*)yout;
            o[warp * 4 + h * 2 + 0] = make_float4(a[0], a[1], a[2], a[3]);
            o[warp * 4 + h * 2 + 1] = make_float4(a[4], a[5], a[6], a[7]);
        }
        return;
    }
    // softmax over 16 features split across h=0/1
#pragma unroll
    for (int t = 0; t < 8; t++) a[t] += bsm[h * 8 + t];
    float m = a[0];
#pragma unroll
    for (int t = 1; t < 8; t++) m = fmaxf(m, a[t]);
    m = fmaxf(m, __shfl_xor_sync(0xffffffffu, m, 1));
    float s = 0.0f;
#pragma unroll
    for (int t = 0; t < 8; t++) { a[t] = __expf(a[t] - m); s += a[t]; }
    s += __shfl_xor_sync(0xffffffffu, s, 1);
    float inv = 1.0f / s;
#pragma unroll
    for (int t = 0; t < 8; t++) a[t] *= inv;

    if (MODE == 1) {
        if (lane < 2) {
            uint4 u;
            *reinterpret_cast<__half2*>(&u.x) = __floats2half2_rn(a[0] * d, a[1] * d);
            *reinterpret_cast<__half2*>(&u.y) = __floats2half2_rn(a[2] * d, a[3] * d);
            *reinterpret_cast<__half2*>(&u.z) = __floats2half2_rn(a[4] * d, a[5] * d);
            *reinterpret_cast<__half2*>(&u.w) = __floats2half2_rn(a[6] * d, a[7] * d);
            ((uint4*)yout)[warp * 2 + h] = u;
        }
    } else {
        if (lane < 2) {
            float4* o = (float4*)yout;
            o[warp * 4 + h * 2 + 0] = make_float4(a[0], a[1], a[2], a[3]);
            o[warp * 4 + h * 2 + 1] = make_float4(a[4], a[5], a[6], a[7]);
        }
    }
}

// D=32 (fp16 rows, 64B): 4 lanes/row-quarter, 4-wide pipelined -> 32 edges in flight.
__global__ void k_agg32h(const __half* __restrict__ xin, float* __restrict__ yout) {
    int warp = (blockIdx.x * blockDim.x + threadIdx.x) >> 5;
    if (warp >= NN) return;
    int lane = threadIdx.x & 31;
    int h = lane & 3;
    int ei = lane >> 2;
    int beg = __ldg(&g_rowptr[warp]);
    int end = __ldg(&g_rowptr[warp + 1]);
    const uint4* __restrict__ x4 = (const uint4*)xin;

    float a[8] = {0, 0, 0, 0, 0, 0, 0, 0};
    if (ei == 0) acc_h8(x4[warp * 4 + h], a);

    for (int e = beg + ei; e < end; e += 32) {
        int e1 = e + 8, e2 = e + 16, e3 = e + 24;
        bool v1 = e1 < end, v2 = e2 < end, v3 = e3 < end;
        int s0 = __ldg(&g_csr_src[e]);
        int s1 = v1 ? __ldg(&g_csr_src[e1]) : 0;
        int s2 = v2 ? __ldg(&g_csr_src[e2]) : 0;
        int s3 = v3 ? __ldg(&g_csr_src[e3]) : 0;
        uint4 r0 = x4[s0 * 4 + h];
        uint4 r1 = x4[s1 * 4 + h];
        uint4 r2 = x4[s2 * 4 + h];
        uint4 r3 = x4[s3 * 4 + h];
        acc_h8(r0, a);
        if (v1) acc_h8(r1, a);
        if (v2) acc_h8(r2, a);
        if (v3) acc_h8(r3, a);
    }

    red8(a, 4); red8(a, 8); red8(a, 16);

    float d = g_dis[warp];
    if (lane < 4) {
        float4* o = (float4*)yout;
        o[warp * 8 + h * 2 + 0] = make_float4(a[0] * d, a[1] * d, a[2] * d, a[3] * d);
        o[warp * 8 + h * 2 + 1] = make_float4(a[4] * d, a[5] * d, a[6] * d, a[7] * d);
    }
}

// ---------------- fused per-node GEMM: z = relu(y@W1 + b1) @ W2, out half dis-scaled ----------------
__global__ void k_gemm_fused(const float* __restrict__ yin, __half* __restrict__ zout,
                             const float* __restrict__ W1, const float* __restrict__ b1,
                             const float* __restrict__ W2) {
    __shared__ float W1s[16 * 64];
    __shared__ float W2s[64 * 32];
    __shared__ float b1s[64];
    for (int k = threadIdx.x; k < 16 * 64; k += blockDim.x) W1s[k] = W1[k];
    for (int k = threadIdx.x; k < 64 * 32; k += blockDim.x) W2s[k] = W2[k];
    for (int k = threadIdx.x; k < 64; k += blockDim.x) b1s[k] = b1[k];
    __syncthreads();

    int i = blockIdx.x * blockDim.x + threadIdx.x;
    if (i >= NN) return;

    float xr[16];
#pragma unroll
    for (int m = 0; m < 4; m++) {
        float4 v = ((const float4*)yin)[i * 4 + m];
        xr[m * 4 + 0] = v.x; xr[m * 4 + 1] = v.y; xr[m * 4 + 2] = v.z; xr[m * 4 + 3] = v.w;
    }
    float z[32];
#pragma unroll
    for (int j = 0; j < 32; j++) z[j] = 0.0f;

    for (int k = 0; k < 64; k++) {
        float t = b1s[k];
#pragma unroll
        for (int m = 0; m < 16; m++) t += xr[m] * W1s[m * 64 + k];
        t = fmaxf(t, 0.0f);
#pragma unroll
        for (int j = 0; j < 32; j++) z[j] += t * W2s[k * 32 + j];
    }

    float d = g_dis[i];
    __half2* o = ((__half2*)zout) + i * 16;
#pragma unroll
    for (int j = 0; j < 16; j++)
        o[j] = __floats2half2_rn(z[2 * j] * d, z[2 * j + 1] * d);
}

// ---------------- gemm3: h = relu(z + b2) @ W3, out half dis-scaled (d16) ----------------
__global__ void k_gemm3(const float* __restrict__ zin, __half* __restrict__ hout,
                        const float* __restrict__ b2, const float* __restrict__ W3) {
    __shared__ float W3s[32 * 16];
    __shared__ float b2s[32];
    for (int k = threadIdx.x; k < 32 * 16; k += blockDim.x) W3s[k] = W3[k];
    for (int k = threadIdx.x; k < 32; k += blockDim.x) b2s[k] = b2[k];
    __syncthreads();

    int i = blockIdx.x * blockDim.x + threadIdx.x;
    if (i >= NN) return;

    float acc[16];
#pragma unroll
    for (int j = 0; j < 16; j++) acc[j] = 0.0f;

#pragma unroll
    for (int m = 0; m < 8; m++) {
        float4 v = ((const float4*)zin)[i * 8 + m];
        float vv[4] = {v.x, v.y, v.z, v.w};
#pragma unroll
        for (int q = 0; q < 4; q++) {
            int k = m * 4 + q;
            float t = fmaxf(vv[q] + b2s[k], 0.0f);
#pragma unroll
            for (int j = 0; j < 16; j++) acc[j] += t * W3s[k * 16 + j];
        }
    }

    float d = g_dis[i];
    __half2* o = ((__half2*)hout) + i * 8;
#pragma unroll
    for (int j = 0; j < 8; j++)
        o[j] = __floats2half2_rn(acc[2 * j] * d, acc[2 * j + 1] * d);
}

// ---------------- launch ----------------
extern "C" void kernel_launch(void* const* d_in, const int* in_sizes, int n_in,
                              void* d_out, int out_size) {
    const float* x  = (const float*)d_in[0];
    const int*   ei = (const int*)d_in[1];
    const int*   src = ei;
    const int*   dst = ei + EE;
    const float* W1 = (const float*)d_in[2];
    const float* b1 = (const float*)d_in[3];
    const float* W2 = (const float*)d_in[4];
    const float* b2 = (const float*)d_in[5];
    const float* W3 = (const float*)d_in[6];
    const float* b3 = (const float*)d_in[7];
    float* out = (float*)d_out;

    __half *pHX, *pH1, *pH2;
    float *pF;
    int *pCnt;
    cudaGetSymbolAddress((void**)&pHX, g_hx);
    cudaGetSymbolAddress((void**)&pH1, g_h1);
    cudaGetSymbolAddress((void**)&pH2, g_h2);
    cudaGetSymbolAddress((void**)&pF, g_f);
    cudaGetSymbolAddress((void**)&pCnt, g_cnt);

    const int TB = 256;
    const int gN = (NN + TB - 1) / TB;
    const int gE = (EE + TB - 1) / TB;
    const int gW = (NN * 32 + TB - 1) / TB;   // warp-per-node
    const int gG = (NN + 127) / 128;

    // CSR build + prescale
    cudaMemsetAsync(pCnt, 0, NN * sizeof(int));
    k_hist<<<gE, TB>>>(dst);
    k_scan1<<<NBLK, 1024>>>();
    k_scan2<<<1, 32>>>();
    k_finalize<<<gN, TB>>>();
    k_scatter<<<gE, TB>>>(src, dst);
    k_prescale<<<gG, 128>>>(x);

    for (int blk = 0; blk < 5; blk++) {
        // layer1 agg (d16): y = dis*(sum x~)  [fp32]
        k_agg16h<0><<<gW, TB>>>(pHX, pF, nullptr);
        // fused gemm 16->64->32, relu, out = dis * (relu(yW1+b1)W2)  [fp16]
        k_gemm_fused<<<gG, 128>>>(pF, pH1, W1 + blk * 16 * 64, b1 + blk * 64,
                                  W2 + blk * 64 * 32);
        // layer2 agg (d32): z = dis*(sum y~)  [fp32]
        k_agg32h<<<gW, TB>>>(pH1, pF);
        // gemm3: h~ = dis * (relu(z+b2)W3)  [fp16]
        k_gemm3<<<gG, 128>>>(pF, pH2, b2 + blk * 32, W3 + blk * 32 * 16);
        // layer3 agg (d16) + softmax
        if (blk == 4)
            k_agg16h<2><<<gW, TB>>>(pH2, out, b3 + blk * 16);
        else
            k_agg16h<1><<<gW, TB>>>(pH2, pHX, b3 + blk * 16);
    }
}